// round 1
// baseline (speedup 1.0000x reference)
#include <cuda_runtime.h>
#include <math.h>

#define NSEQ 2048
#define HDIM 1024
#define NHEAD 16
#define DH 64
#define S2 1024        // 2 * span
#define SPAN 512
#define INV_SCALE 0.0721687836487032f   // 1/sqrt(64*3)

// ---------------- scratch (device globals; no allocations allowed) ----------
__device__ float g_Q[NHEAD * NSEQ * DH];
__device__ float g_K[NHEAD * NSEQ * DH];
__device__ float g_V[NHEAD * NSEQ * DH];
__device__ float g_PosK[NHEAD * S2 * DH];
__device__ float g_PosQ[NHEAD * S2 * DH];
__device__ float g_c2p[(size_t)NHEAD * NSEQ * S2];   // 134 MB
__device__ float g_p2c[(size_t)NHEAD * NSEQ * S2];   // 134 MB
__device__ float g_sc [(size_t)NHEAD * NSEQ * NSEQ]; // 268 MB (scores -> probs in place)

// ---------------------------------------------------------------------------
// NT GEMM core: C[m][n] = sum_k A[m][k] * B[n][k]
// BM=128, BN=16*TN, BK=16, 256 threads, per-thread tile 8 x TN.
// All M/N/K here are multiples of the tile sizes (no bounds checks needed).
// ---------------------------------------------------------------------------
template <int TN>
__device__ __forceinline__ void gemm_nt_body(const float* __restrict__ A,
                                             const float* __restrict__ B,
                                             int K, int lda, int ldb,
                                             int m0, int n0,
                                             float (&acc)[8][TN]) {
    constexpr int BN = 16 * TN;
    __shared__ float As[16][132];
    __shared__ float Bs[16][BN + 4];
    const int t  = threadIdx.x;
    const int ty = t >> 4;
    const int tx = t & 15;

#pragma unroll
    for (int i = 0; i < 8; i++)
#pragma unroll
        for (int j = 0; j < TN; j++) acc[i][j] = 0.0f;

    for (int kt = 0; kt < K; kt += 16) {
        // load A tile (128 x 16), transposed into As[k][m]
#pragma unroll
        for (int i = 0; i < 8; i++) {
            int lin = i * 256 + t;
            int r = lin >> 4, c = lin & 15;
            As[c][r] = A[(m0 + r) * lda + kt + c];
        }
        // load B tile (BN x 16), transposed into Bs[k][n]
#pragma unroll
        for (int i = 0; i < (BN * 16) / 256; i++) {
            int lin = i * 256 + t;
            int r = lin >> 4, c = lin & 15;
            Bs[c][r] = B[(n0 + r) * ldb + kt + c];
        }
        __syncthreads();
#pragma unroll
        for (int kk = 0; kk < 16; kk++) {
            float a[8], b[TN];
            *(float4*)&a[0] = *(const float4*)&As[kk][ty * 8];
            *(float4*)&a[4] = *(const float4*)&As[kk][ty * 8 + 4];
            if constexpr (TN == 8) {
                *(float4*)&b[0] = *(const float4*)&Bs[kk][tx * 8];
                *(float4*)&b[4] = *(const float4*)&Bs[kk][tx * 8 + 4];
            } else {
                *(float4*)&b[0] = *(const float4*)&Bs[kk][tx * 4];
            }
#pragma unroll
            for (int i = 0; i < 8; i++)
#pragma unroll
                for (int j = 0; j < TN; j++)
                    acc[i][j] = fmaf(a[i], b[j], acc[i][j]);
        }
        __syncthreads();
    }
}

// ---------------------------------------------------------------------------
// NN GEMM core for PV: C[m][n] = sum_k A[m][k] * B[k][n], BN = 64, TN = 4
// ---------------------------------------------------------------------------
__device__ __forceinline__ void gemm_nn_body_64(const float* __restrict__ A,
                                                const float* __restrict__ B,
                                                int K, int lda, int ldb,
                                                int m0, int n0,
                                                float (&acc)[8][4]) {
    __shared__ float As[16][132];
    __shared__ float Bs[16][68];
    const int t  = threadIdx.x;
    const int ty = t >> 4;
    const int tx = t & 15;

#pragma unroll
    for (int i = 0; i < 8; i++)
#pragma unroll
        for (int j = 0; j < 4; j++) acc[i][j] = 0.0f;

    for (int kt = 0; kt < K; kt += 16) {
#pragma unroll
        for (int i = 0; i < 8; i++) {
            int lin = i * 256 + t;
            int r = lin >> 4, c = lin & 15;
            As[c][r] = A[(m0 + r) * lda + kt + c];
        }
        // B tile: 16 x 64, already [k][n] layout -> direct
#pragma unroll
        for (int i = 0; i < 4; i++) {
            int lin = i * 256 + t;
            int kr = lin >> 6, nc = lin & 63;
            Bs[kr][nc] = B[(kt + kr) * ldb + n0 + nc];
        }
        __syncthreads();
#pragma unroll
        for (int kk = 0; kk < 16; kk++) {
            float a[8], b[4];
            *(float4*)&a[0] = *(const float4*)&As[kk][ty * 8];
            *(float4*)&a[4] = *(const float4*)&As[kk][ty * 8 + 4];
            *(float4*)&b[0] = *(const float4*)&Bs[kk][tx * 4];
#pragma unroll
            for (int i = 0; i < 8; i++)
#pragma unroll
                for (int j = 0; j < 4; j++)
                    acc[i][j] = fmaf(a[i], b[j], acc[i][j]);
        }
        __syncthreads();
    }
}

// ---------------------------------------------------------------------------
// K1: fused QKV projection.  qp = hidden @ W^T ; per-head 192-channel split:
// head h = c/192, j = c%192: j<64 -> Q (+bias, /scale), <128 -> K, else V (+bias)
// ---------------------------------------------------------------------------
__global__ void __launch_bounds__(256) qkv_kernel(const float* __restrict__ hidden,
                                                  const float* __restrict__ W,
                                                  const float* __restrict__ qb,
                                                  const float* __restrict__ vb) {
    float acc[8][8];
    const int m0 = blockIdx.y * 128;
    const int n0 = blockIdx.x * 128;
    gemm_nt_body<8>(hidden, W, HDIM, HDIM, HDIM, m0, n0, acc);
    const int ty = threadIdx.x >> 4, tx = threadIdx.x & 15;
#pragma unroll
    for (int i = 0; i < 8; i++) {
        int m = m0 + ty * 8 + i;
#pragma unroll
        for (int j = 0; j < 8; j++) {
            int cg = n0 + tx * 8 + j;
            int h  = cg / 192;
            int jj = cg - h * 192;
            float val = acc[i][j];
            if (jj < 64)
                g_Q[(h * NSEQ + m) * DH + jj] = (val + qb[h * 64 + jj]) * INV_SCALE;
            else if (jj < 128)
                g_K[(h * NSEQ + m) * DH + (jj - 64)] = val;
            else
                g_V[(h * NSEQ + m) * DH + (jj - 128)] = val + vb[h * 64 + (jj - 128)];
        }
    }
}

// ---------------------------------------------------------------------------
// K2: position projections.  which=0: PosK = rel @ Wk^T
//                            which=1: PosQ = (rel @ Wq^T + b) / scale
// head-split layout: [h][s][d] with c = h*64+d
// ---------------------------------------------------------------------------
__global__ void __launch_bounds__(256) pos_kernel(const float* __restrict__ rel,
                                                  const float* __restrict__ W,
                                                  const float* __restrict__ bias,
                                                  int which) {
    float acc[8][8];
    const int m0 = blockIdx.y * 128;   // s
    const int n0 = blockIdx.x * 128;   // c
    gemm_nt_body<8>(rel, W, HDIM, HDIM, HDIM, m0, n0, acc);
    const int ty = threadIdx.x >> 4, tx = threadIdx.x & 15;
#pragma unroll
    for (int i = 0; i < 8; i++) {
        int s = m0 + ty * 8 + i;
#pragma unroll
        for (int j = 0; j < 8; j++) {
            int c = n0 + tx * 8 + j;
            int h = c >> 6, d = c & 63;
            if (which == 0)
                g_PosK[(h * S2 + s) * DH + d] = acc[i][j];
            else
                g_PosQ[(h * S2 + s) * DH + d] = (acc[i][j] + bias[c]) * INV_SCALE;
        }
    }
}

// ---------------------------------------------------------------------------
// K3: raw relative scores (batched over heads).
// which=0: c2p_raw[h][q][s] = Q[h][q] . PosK[h][s]   (Q already scaled)
// which=1: p2c_raw[h][k][s] = K[h][k] . PosQ[h][s]   (PosQ already scaled)
// ---------------------------------------------------------------------------
__global__ void __launch_bounds__(256) relsc_kernel(int which) {
    const int h  = blockIdx.z;
    const int m0 = blockIdx.y * 128;
    const int n0 = blockIdx.x * 128;
    const float* A = (which == 0 ? g_Q : g_K) + h * NSEQ * DH;
    const float* B = (which == 0 ? g_PosK : g_PosQ) + h * S2 * DH;
    float* O = (which == 0 ? g_c2p : g_p2c);
    float acc[8][8];
    gemm_nt_body<8>(A, B, DH, DH, DH, m0, n0, acc);
    const int ty = threadIdx.x >> 4, tx = threadIdx.x & 15;
#pragma unroll
    for (int i = 0; i < 8; i++) {
        int m = m0 + ty * 8 + i;
#pragma unroll
        for (int j = 0; j < 8; j++) {
            int n = n0 + tx * 8 + j;
            O[((size_t)(h * NSEQ + m)) * S2 + n] = acc[i][j];
        }
    }
}

// ---------------------------------------------------------------------------
// K4: content-content scores + fused disentangled-bias gathers + mask.
// idx = clip(relpos[q][k] + span, 0, 2span-1) shared by both gathers.
// ---------------------------------------------------------------------------
__global__ void __launch_bounds__(256) scores_kernel(const int* __restrict__ relpos,
                                                     const int* __restrict__ mask) {
    const int h  = blockIdx.z;
    const int m0 = blockIdx.y * 128;
    const int n0 = blockIdx.x * 128;
    float acc[8][8];
    gemm_nt_body<8>(g_Q + h * NSEQ * DH, g_K + h * NSEQ * DH, DH, DH, DH, m0, n0, acc);
    const int ty = threadIdx.x >> 4, tx = threadIdx.x & 15;
#pragma unroll
    for (int i = 0; i < 8; i++) {
        int q = m0 + ty * 8 + i;
#pragma unroll
        for (int j = 0; j < 8; j++) {
            int kc = n0 + tx * 8 + j;
            int rp  = relpos[q * NSEQ + kc];
            int idx = rp + SPAN;
            idx = idx < 0 ? 0 : (idx > S2 - 1 ? S2 - 1 : idx);
            float val = acc[i][j]
                      + g_c2p[((size_t)(h * NSEQ + q)) * S2 + idx]
                      + g_p2c[((size_t)(h * NSEQ + kc)) * S2 + idx];
            if (mask[q * NSEQ + kc] == 0) val = -1e30f;
            g_sc[((size_t)(h * NSEQ + q)) * NSEQ + kc] = val;
        }
    }
}

// ---------------------------------------------------------------------------
// K5: row softmax (in place) + mask-zeroing.  One block per (h, q) row.
// ---------------------------------------------------------------------------
__global__ void __launch_bounds__(256) softmax_kernel(const int* __restrict__ mask) {
    const int row = blockIdx.x;              // h*NSEQ + q
    const int q   = row & (NSEQ - 1);
    const size_t base = (size_t)row * NSEQ;
    const int t = threadIdx.x;
    __shared__ float red[16];

    float v[8];
    float mx = -INFINITY;
#pragma unroll
    for (int i = 0; i < 8; i++) {
        v[i] = g_sc[base + t + i * 256];
        mx = fmaxf(mx, v[i]);
    }
#pragma unroll
    for (int o = 16; o > 0; o >>= 1) mx = fmaxf(mx, __shfl_xor_sync(0xffffffffu, mx, o));
    if ((t & 31) == 0) red[t >> 5] = mx;
    __syncthreads();
    float rowmax = red[0];
#pragma unroll
    for (int i = 1; i < 8; i++) rowmax = fmaxf(rowmax, red[i]);

    float s = 0.0f;
#pragma unroll
    for (int i = 0; i < 8; i++) {
        v[i] = __expf(v[i] - rowmax);
        s += v[i];
    }
#pragma unroll
    for (int o = 16; o > 0; o >>= 1) s += __shfl_xor_sync(0xffffffffu, s, o);
    if ((t & 31) == 0) red[8 + (t >> 5)] = s;
    __syncthreads();
    float tot = 0.0f;
#pragma unroll
    for (int i = 0; i < 8; i++) tot += red[8 + i];
    float inv = 1.0f / tot;
#pragma unroll
    for (int i = 0; i < 8; i++) {
        int kc = t + i * 256;
        float p = v[i] * inv;
        if (mask[q * NSEQ + kc] == 0) p = 0.0f;
        g_sc[base + kc] = p;
    }
}

// ---------------------------------------------------------------------------
// K6: ctx = probs @ V, fused output transpose to [n][h*64+d]
// ---------------------------------------------------------------------------
__global__ void __launch_bounds__(256) pv_kernel(float* __restrict__ out) {
    const int h  = blockIdx.z;
    const int m0 = blockIdx.y * 128;
    float acc[8][4];
    gemm_nn_body_64(g_sc + (size_t)h * NSEQ * NSEQ, g_V + h * NSEQ * DH,
                    NSEQ, NSEQ, DH, m0, 0, acc);
    const int ty = threadIdx.x >> 4, tx = threadIdx.x & 15;
#pragma unroll
    for (int i = 0; i < 8; i++) {
        int m = m0 + ty * 8 + i;
#pragma unroll
        for (int j = 0; j < 4; j++) {
            int d = tx * 4 + j;
            out[m * HDIM + h * DH + d] = acc[i][j];
        }
    }
}

// ---------------------------------------------------------------------------
extern "C" void kernel_launch(void* const* d_in, const int* in_sizes, int n_in,
                              void* d_out, int out_size) {
    const float* hidden   = (const float*)d_in[0];
    const int*   mask     = (const int*)  d_in[1];
    const int*   relpos   = (const int*)  d_in[2];
    const float* rel_emb  = (const float*)d_in[3];
    const float* in_proj  = (const float*)d_in[4];
    const float* q_bias   = (const float*)d_in[5];
    const float* v_bias   = (const float*)d_in[6];
    const float* pos_w    = (const float*)d_in[7];
    const float* pos_q_w  = (const float*)d_in[8];
    const float* pos_q_b  = (const float*)d_in[9];
    float* out = (float*)d_out;

    // K1: QKV projection  (M=2048, N=3072, K=1024)
    qkv_kernel<<<dim3(3072 / 128, 2048 / 128), 256>>>(hidden, in_proj, q_bias, v_bias);

    // K2: position projections (M=1024, N=1024, K=1024) x2
    pos_kernel<<<dim3(HDIM / 128, S2 / 128), 256>>>(rel_emb, pos_w,   pos_q_b, 0);
    pos_kernel<<<dim3(HDIM / 128, S2 / 128), 256>>>(rel_emb, pos_q_w, pos_q_b, 1);

    // K3: c2p_raw / p2c_raw  (per head: M=2048, N=1024, K=64)
    relsc_kernel<<<dim3(S2 / 128, NSEQ / 128, NHEAD), 256>>>(0);
    relsc_kernel<<<dim3(S2 / 128, NSEQ / 128, NHEAD), 256>>>(1);

    // K4: scores = QK^T + c2p + p2c, masked  (per head: M=N=2048, K=64)
    scores_kernel<<<dim3(NSEQ / 128, NSEQ / 128, NHEAD), 256>>>(relpos, mask);

    // K5: softmax rows
    softmax_kernel<<<NHEAD * NSEQ, 256>>>(mask);

    // K6: probs @ V + output transpose  (per head: M=2048, N=64, K=2048)
    pv_kernel<<<dim3(1, NSEQ / 128, NHEAD), 256>>>(out);
}